// round 17
// baseline (speedup 1.0000x reference)
#include <cuda_runtime.h>
#include <cuda_bf16.h>

#define NIMG  4
#define KCH   21
#define NPIX  4096      // 64*64
#define TILE  128
#define NPAIR 528       // max tile-pairs per image
#define HW    16384     // 128*128
#define KPAD  64        // bf16 K row padding in global scratch
#define ROWW  40        // seg smem row width in bf16 (80B, conflict-free)
#define FROW  48        // feat smem row bytes (conflict-free ldmatrix)
#define SVW   33        // transpose smem row stride (floats)
#define GRIDE 296       // persistent grid (2 CTAs x 148 SMs, all resident)

// q-side buffer layout (bytes)
#define OFF_SB   0
#define OFF_SFB  (TILE * ROWW * 2)              // 10240
#define OFF_QSG  (OFF_SFB + TILE * FROW)        // 16384
#define BUFSZ    (OFF_QSG + 64 * 16)            // 17408

typedef unsigned long long u64;
typedef unsigned int       u32;
typedef unsigned short     u16;

#define CEXP  (-0.72134752044448170f)   // -0.5 * log2(e)
#define LOG2E ( 1.44269504088896340f)

// ---- device scratch (rows [NPIX..NPIX+8) never written => stay zero) ----
__device__ __nv_bfloat16 g_sb[NIMG][NPIX + 8][KPAD]; // seg*roi bf16, k 21..31 zero
__device__ u32   g_fA[NIMG][NPIX + 8][8];            // bf16 row [hi(5),hi(5),lo(5),0]
__device__ u32   g_fB[NIMG][NPIX + 8][8];            // bf16 row [hi(5),lo(5),hi(5),0]
__device__ float g_pq[NIMG][NPIX + 8][2];            // (CEXP*|f|^2, gate)
__device__ int   g_idx[NIMG][NPIX];                  // compacted roi=1 pixel ids
__device__ int   g_nt [NIMG];
__device__ float g_partial[NIMG * NPAIR];
__device__ int   g_ctr;                              // completion counter
__device__ int   g_bar;                              // grid barrier counter

// ---- packed f32x2 helpers ----
__device__ __forceinline__ u64 pk2(float lo, float hi) {
    u64 r; asm("mov.b64 %0, {%1, %2};" : "=l"(r) : "f"(lo), "f"(hi)); return r;
}
__device__ __forceinline__ void unpk2(u64 v, float& lo, float& hi) {
    asm("mov.b64 {%0, %1}, %2;" : "=f"(lo), "=f"(hi) : "l"(v));
}
#define FMA2(d, a, b, c) asm("fma.rn.f32x2 %0, %1, %2, %3;" : "=l"(d) : "l"(a), "l"(b), "l"(c))
#define MUL2(d, a, b)    asm("mul.rn.f32x2 %0, %1, %2;"     : "=l"(d) : "l"(a), "l"(b))
#define ADD2(d, a, b)    asm("add.rn.f32x2 %0, %1, %2;"     : "=l"(d) : "l"(a), "l"(b))
__device__ __forceinline__ float ex2(float x) {
    float r; asm("ex2.approx.f32 %0, %1;" : "=f"(r) : "f"(x)); return r;
}
__device__ __forceinline__ u32 smem_u32(const void* p) {
    u32 a; asm("{ .reg .u64 t; cvta.to.shared.u64 t, %1; cvt.u32.u64 %0, t; }" : "=r"(a) : "l"(p));
    return a;
}
__device__ __forceinline__ u32 bf16pair(float lo, float hi) {   // lo -> bits[0:16)
    u32 r; asm("cvt.rn.bf16x2.f32 %0, %1, %2;" : "=r"(r) : "f"(hi), "f"(lo)); return r;
}
#define LDMX4(r, addr) \
    asm volatile("ldmatrix.sync.aligned.m8n8.x4.shared.b16 {%0,%1,%2,%3}, [%4];" \
        : "=r"((r)[0]), "=r"((r)[1]), "=r"((r)[2]), "=r"((r)[3]) : "r"(addr))
#define MMA16816(d0,d1,d2,d3,a0,a1,a2,a3,b0,b1) \
    asm volatile("mma.sync.aligned.m16n8k16.row.col.f32.bf16.bf16.f32 " \
        "{%0,%1,%2,%3}, {%4,%5,%6,%7}, {%8,%9}, {%0,%1,%2,%3};" \
        : "+f"(d0), "+f"(d1), "+f"(d2), "+f"(d3) \
        : "r"(a0), "r"(a1), "r"(a2), "r"(a3), "r"(b0), "r"(b1))

// ---- gathered fills ----
__device__ __forceinline__ void fill_A(char* sA, int tid, int n, int p0)
{
    int r = tid >> 2, c = tid & 3;
    int ip = g_idx[n][p0 + r];
    *(uint4*)(sA + r * (ROWW * 2) + c * 16) = *(const uint4*)&g_sb[n][ip][c * 8];
}
__device__ __forceinline__ void fill_q(char* buf, int tid, int n, int q0, bool diag)
{
    {
        int r = tid >> 2, c = tid & 3;
        int iq = g_idx[n][q0 + r];
        *(uint4*)(buf + OFF_SB + r * (ROWW * 2) + c * 16) = *(const uint4*)&g_sb[n][iq][c * 8];
    }
    if (tid < 256) {
        int r = tid >> 1, h = tid & 1;
        int iq = g_idx[n][q0 + r];
        *(uint4*)(buf + OFF_SFB + r * FROW + h * 16) = *(const uint4*)&g_fB[n][iq][h * 4];
    }
    if (tid < 64) {
        int iq0 = g_idx[n][q0 + 2 * tid];
        int iq1 = g_idx[n][q0 + 2 * tid + 1];
        float2 e = *(const float2*)&g_pq[n][iq0][0];
        float2 o = *(const float2*)&g_pq[n][iq1][0];
        u64* q = (u64*)(buf + OFF_QSG) + 2 * tid;
        q[0] = pk2(e.x, o.x);
        q[1] = pk2(diag ? 0.0f : e.y, diag ? 0.0f : o.y);
    }
}

// ---- one tt step of the math core (R13/R16-proven body) ----
#define TT_STEP(tt) do {                                                      \
    u32 bfr[4];                                                               \
    LDMX4(bfr, baddr + (tt) * (8 * ROWW * 2));                                \
    if (((tt) & 1) == 0) LDMX4(bfeat, fbaddr + (tt) * (8 * FROW));            \
    u32 b0f = ((tt) & 1) ? bfeat[2] : bfeat[0];                               \
    u32 b1f = ((tt) & 1) ? bfeat[3] : bfeat[1];                               \
    float d0 = 0.f, d1 = 0.f, d2_ = 0.f, d3 = 0.f;                            \
    MMA16816(d0, d1, d2_, d3, afr[0][0], afr[0][1], afr[0][2], afr[0][3], bfr[0], bfr[1]); \
    MMA16816(d0, d1, d2_, d3, afr[1][0], afr[1][1], afr[1][2], afr[1][3], bfr[2], bfr[3]); \
    float e0 = 0.f, e1 = 0.f, e2 = 0.f, e3 = 0.f;                             \
    MMA16816(e0, e1, e2, e3, afeat[0], afeat[1], afeat[2], afeat[3], b0f, b1f); \
    ulonglong2 qv = *(const ulonglong2*)&qsgp[2 * (nhalf * 32 + (tt) * 4 + lm4)]; \
    _Pragma("unroll")                                                         \
    for (int r = 0; r < 2; r++) {                                             \
        u64 dotp = r ? pk2(e2, e3) : pk2(e0, e1);                             \
        u64 s2; ADD2(s2, sps[r], qv.x);                                       \
        u64 t2; FMA2(t2, dotp, l2e, s2);                                      \
        float tlo, thi; unpk2(t2, tlo, thi);                                  \
        u64 ee = pk2(ex2(tlo), ex2(thi));                                     \
        u64 cf; ADD2(cf, gp2[r], qv.y);                                       \
        u64 wv; MUL2(wv, ee, cf);                                             \
        u64 cc = r ? pk2(d2_, d3) : pk2(d0, d1);                              \
        if (r) { FMA2(accB, wv, cc, accB); }                                  \
        else   { FMA2(accA, wv, cc, accA); }                                  \
    }                                                                         \
} while (0)

// ---------------------------------------------------------------------------
// ONE persistent kernel: phase A (prep/compact), volatile-spin grid barrier,
// phase B = R16 pipelined energy loop (verbatim).
// ---------------------------------------------------------------------------
__global__ __launch_bounds__(512, 2) void fused_kernel(float* __restrict__ out,
                                                       const float* __restrict__ images,
                                                       const float* __restrict__ segs,
                                                       const float* __restrict__ rois,
                                                       const int*   __restrict__ labels)
{
    __shared__ __align__(16) char sA[TILE * ROWW * 2];   // p-side seg (single, pipelined)
    __shared__ __align__(16) char pool[2][BUFSZ];        // q-side double buffer
    __shared__ float red[16];
    __shared__ int   warp_sums[16];
    __shared__ int   s_cnt;
    __shared__ int   lastflag;

    int b   = blockIdx.x;
    int tid = threadIdx.x;
    int w = tid >> 5, lane = tid & 31;

    // ================= PHASE A =================
    if (b < NIMG * 64) {
        float (*sv)[SVW] = (float(*)[SVW])&pool[0][0];   // 8448B, aliased
        float* sroi      = (float*)&pool[0][8448];
        int n = b >> 6, y = b & 63;

        for (int i = tid; i < 64 * 11; i += 512) {
            int x = i / 11, k = 21 + (i % 11);
            sv[x][k] = 0.0f;
        }

        const float* segbase = segs + (size_t)n * KCH * HW + (2 * y) * 128;
        #pragma unroll
        for (int kb = 0; kb < 32; kb += 16) {
            int k = kb + (tid >> 5);
            int t = lane;
            if (k < KCH) {
                const float* sp = segbase + (size_t)k * HW + 4 * t;
                float4 a0 = *(const float4*)sp;
                float4 a1 = *(const float4*)(sp + 128);
                sv[2 * t][k]     = 0.25f * ((a0.x + a0.y) + (a1.x + a1.y));
                sv[2 * t + 1][k] = 0.25f * ((a0.z + a0.w) + (a1.z + a1.w));
            }
        }
        if (tid < 64) sroi[tid] = rois[n * HW + 2 * y * 128 + 2 * tid];
        __syncthreads();

        if (tid < 256) {
            int x = tid >> 2, c = tid & 3;
            float roi = sroi[x];
            u32 wb[4];
            #pragma unroll
            for (int j = 0; j < 4; j++) {
                float v0 = sv[x][c * 8 + 2 * j]     * roi;
                float v1 = sv[x][c * 8 + 2 * j + 1] * roi;
                wb[j] = bf16pair(v0, v1);
            }
            *(uint4*)&g_sb[n][y * 64 + x][c * 8] = make_uint4(wb[0], wb[1], wb[2], wb[3]);
        }

        if (tid < 64) {
            int x = tid;
            float mx = sv[x][0];
            #pragma unroll
            for (int k = 1; k < KCH; k++) mx = fmaxf(mx, sv[x][k]);
            float roi = sroi[x];
            int p = y * 64 + x;
            int src = 2 * y * 128 + 2 * x;
            int lbl = labels[n * HW + src];
            float gate = fmaxf((lbl == 255) ? 1.0f : (roi - mx), 0.0f);

            const float* ib = images + (size_t)n * 3 * HW + src;
            float f[5];
            f[0] = (float)x * (1.0f / 50.0f);
            f[1] = (float)y * (1.0f / 50.0f);
            f[2] = ib[0]      * (1.0f / 15.0f);
            f[3] = ib[HW]     * (1.0f / 15.0f);
            f[4] = ib[2 * HW] * (1.0f / 15.0f);
            float sq = f[0]*f[0] + f[1]*f[1] + f[2]*f[2] + f[3]*f[3] + f[4]*f[4];
            *(float2*)&g_pq[n][p][0] = make_float2(CEXP * sq, gate);

            u16 h[5], l[5];
            #pragma unroll
            for (int d = 0; d < 5; d++) {
                __nv_bfloat16 hb = __float2bfloat16(f[d]);
                __nv_bfloat16 lb = __float2bfloat16(f[d] - __bfloat162float(hb));
                h[d] = *(u16*)&hb; l[d] = *(u16*)&lb;
            }
            u32 aw[8], bw[8];
            aw[0] = h[0] | (u32)h[1] << 16;  aw[1] = h[2] | (u32)h[3] << 16;
            aw[2] = h[4] | (u32)h[0] << 16;  aw[3] = h[1] | (u32)h[2] << 16;
            aw[4] = h[3] | (u32)h[4] << 16;  aw[5] = l[0] | (u32)l[1] << 16;
            aw[6] = l[2] | (u32)l[3] << 16;  aw[7] = l[4];
            bw[0] = h[0] | (u32)h[1] << 16;  bw[1] = h[2] | (u32)h[3] << 16;
            bw[2] = h[4] | (u32)l[0] << 16;  bw[3] = l[1] | (u32)l[2] << 16;
            bw[4] = l[3] | (u32)l[4] << 16;  bw[5] = h[0] | (u32)h[1] << 16;
            bw[6] = h[2] | (u32)h[3] << 16;  bw[7] = h[4];
            *(uint4*)&g_fA[n][p][0] = make_uint4(aw[0], aw[1], aw[2], aw[3]);
            *(uint4*)&g_fA[n][p][4] = make_uint4(aw[4], aw[5], aw[6], aw[7]);
            *(uint4*)&g_fB[n][p][0] = make_uint4(bw[0], bw[1], bw[2], bw[3]);
            *(uint4*)&g_fB[n][p][4] = make_uint4(bw[4], bw[5], bw[6], bw[7]);
        }
    } else if (b < NIMG * 64 + NIMG) {
        int n = b - NIMG * 64;
        int pbase = tid * 8;

        u32 mask = 0; int c = 0;
        #pragma unroll
        for (int i = 0; i < 8; i++) {
            int p = pbase + i;
            int y = p >> 6, x = p & 63;
            float r = rois[n * HW + (2 * y) * 128 + 2 * x];
            if (r > 0.5f) { mask |= (1u << i); c++; }
        }
        int sc = c;
        #pragma unroll
        for (int o = 1; o < 32; o <<= 1) {
            int v = __shfl_up_sync(0xffffffffu, sc, o);
            if (lane >= o) sc += v;
        }
        if (lane == 31) warp_sums[w] = sc;
        __syncthreads();
        int wb = 0;
        #pragma unroll
        for (int i = 0; i < 16; i++) if (i < w) wb += warp_sums[i];
        int pos = wb + sc - c;
        #pragma unroll
        for (int i = 0; i < 8; i++)
            if (mask & (1u << i)) g_idx[n][pos++] = pbase + i;
        if (tid == 511) s_cnt = wb + sc;
        __syncthreads();
        int cnt = s_cnt;
        int nt = (cnt + 127) >> 7;
        for (int j = cnt + tid; j < nt * 128; j += 512) g_idx[n][j] = NPIX;  // sentinel
        if (tid == 0) g_nt[n] = nt;
    }

    // ================= GRID BARRIER (volatile-load spin, all CTAs resident) ====
    __syncthreads();
    if (tid == 0) {
        __threadfence();                       // release phase-A writes
        atomicAdd(&g_bar, 1);
        volatile int* vb = &g_bar;
        while (*vb < GRIDE) {}
        __threadfence();                       // acquire
    }
    __syncthreads();

    // ================= PHASE B: R16 pipelined energy loop =================
    int pre1, pre2, pre3, total;
    {
        int n0 = g_nt[0], n1 = g_nt[1], n2 = g_nt[2], n3 = g_nt[3];
        pre1 = n0 * (n0 + 1) / 2;
        pre2 = pre1 + n1 * (n1 + 1) / 2;
        pre3 = pre2 + n2 * (n2 + 1) / 2;
        total = pre3 + n3 * (n3 + 1) / 2;
    }

    int m = b;
    bool have = (m < total);
    int n = 0, p0 = 0, q0 = 0; bool diag = false;
    if (have) {
        n = (m >= pre1) + (m >= pre2) + (m >= pre3);
        int t = m - (n == 0 ? 0 : (n == 1 ? pre1 : (n == 2 ? pre2 : pre3)));
        int nt = g_nt[n];
        int ti = 0, rem = t;
        while (rem >= nt - ti) { rem -= nt - ti; ti++; }
        p0 = ti * TILE; q0 = (ti + rem) * TILE; diag = (rem == 0);
        fill_A(sA, tid, n, p0);
        fill_q(&pool[0][0], tid, n, q0, diag);
    }
    __syncthreads();

    int bi = 0;
    while (have) {
        int mn = m + GRIDE;
        bool haveN = (mn < total);
        int nN = 0, p0N = 0, q0N = 0; bool diagN = false;
        if (haveN) {
            nN = (mn >= pre1) + (mn >= pre2) + (mn >= pre3);
            int t = mn - (nN == 0 ? 0 : (nN == 1 ? pre1 : (nN == 2 ? pre2 : pre3)));
            int nt = g_nt[nN];
            int ti = 0, rem = t;
            while (rem >= nt - ti) { rem -= nt - ti; ti++; }
            p0N = ti * TILE; q0N = (ti + rem) * TILE; diagN = (rem == 0);
        }

        char* buf = &pool[bi][0];
        int mstrip = w >> 1, nhalf = w & 1, lm4 = lane & 3;
        u32 sAu  = smem_u32(sA);
        u32 sBu  = smem_u32(buf + OFF_SB);
        u32 sFBu = smem_u32(buf + OFF_SFB);
        const u64* qsgp = (const u64*)(buf + OFF_QSG);

        int rowA0 = mstrip * 16 + (lane >> 2);
        int ip0 = g_idx[n][p0 + rowA0];
        int ip1 = g_idx[n][p0 + rowA0 + 8];
        u64 sps[2], gp2[2];
        {
            float2 v0 = *(const float2*)&g_pq[n][ip0][0];
            float2 v1 = *(const float2*)&g_pq[n][ip1][0];
            sps[0] = pk2(v0.x, v0.x); gp2[0] = pk2(v0.y, v0.y);
            sps[1] = pk2(v1.x, v1.x); gp2[1] = pk2(v1.y, v1.y);
        }
        const u32* F0 = &g_fA[n][ip0][0];
        const u32* F1 = &g_fA[n][ip1][0];
        u32 afeat[4];
        afeat[0] = F0[lm4];     afeat[1] = F1[lm4];
        afeat[2] = F0[4 + lm4]; afeat[3] = F1[4 + lm4];

        u32 afr[2][4];
        {
            int arow = mstrip * 16 + (lane & 7) + ((lane >> 3) & 1) * 8;
            u32 aaddr = sAu + arow * (ROWW * 2) + (lane >> 4) * 16;
            LDMX4(afr[0], aaddr);
            LDMX4(afr[1], aaddr + 32);
        }
        u32 baddr  = sBu  + (nhalf * 64 + (lane & 7)) * (ROWW * 2) + (lane >> 3) * 16;
        u32 fbaddr = sFBu + (nhalf * 64 + (lane & 7) + ((lane >> 4) & 1) * 8) * FROW
                          + ((lane >> 3) & 1) * 16;

        u64 l2e = pk2(LOG2E, LOG2E);
        u64 accA = 0ull, accB = 0ull;
        u32 bfeat[4];

        TT_STEP(0); TT_STEP(1); TT_STEP(2); TT_STEP(3);

        __syncthreads();                       // all sA reads complete
        if (haveN) {                           // prefetch next item under tt=4..7
            fill_A(sA, tid, nN, p0N);
            fill_q(&pool[bi ^ 1][0], tid, nN, q0N, diagN);
        }

        TT_STEP(4); TT_STEP(5); TT_STEP(6); TT_STEP(7);

        u64 acc2; ADD2(acc2, accA, accB);
        float alo, ahi; unpk2(acc2, alo, ahi);
        float acc = alo + ahi;

        #pragma unroll
        for (int o = 16; o > 0; o >>= 1) acc += __shfl_down_sync(0xffffffffu, acc, o);
        if (lane == 0) red[w] = acc;
        __syncthreads();                       // publishes prefetched fills + red
        if (tid == 0) {
            float s = 0.0f;
            #pragma unroll
            for (int v = 0; v < 16; v++) s += red[v];
            g_partial[m] = s;
        }

        m = mn; have = haveN;
        n = nN; p0 = p0N; q0 = q0N; diag = diagN;
        bi ^= 1;
    }

    // ---- per-CTA completion; last CTA reduces ----
    if (tid == 0) {
        __threadfence();
        int v = atomicAdd(&g_ctr, 1);
        lastflag = (v == GRIDE - 1);
    }
    __syncthreads();

    if (lastflag) {
        float s = 0.0f;
        for (int i = tid; i < total; i += 512) s += g_partial[i];
        #pragma unroll
        for (int o = 16; o > 0; o >>= 1) s += __shfl_down_sync(0xffffffffu, s, o);
        if (lane == 0) red[w] = s;
        __syncthreads();
        if (tid == 0) {
            float tot = 0.0f;
            #pragma unroll
            for (int v = 0; v < 16; v++) tot += red[v];
            out[0] = tot * (-1e-7f / (float)NIMG);   // WEIGHT * (-sum / N)
            g_ctr = 0;                               // reset for graph replay
            g_bar = 0;
        }
    }
}

// ---------------------------------------------------------------------------
extern "C" void kernel_launch(void* const* d_in, const int* in_sizes, int n_in,
                              void* d_out, int out_size)
{
    const float* images = (const float*)d_in[0];
    const float* segs   = (const float*)d_in[1];
    const float* rois   = (const float*)d_in[2];
    const int*   labels = (const int*)  d_in[3];

    fused_kernel<<<GRIDE, 512>>>((float*)d_out, images, segs, rois, labels);
}